// round 2
// baseline (speedup 1.0000x reference)
#include <cuda_runtime.h>
#include <math.h>

#define D_DIM 768
#define H_DIM 1024
#define E_NUM 8
#define B_MAX 8192

// ---------------- scratch (device globals; no allocations) ----------------
__device__ int   g_counts[E_NUM];
__device__ int   g_base[E_NUM + 1];
__device__ int   g_tok [E_NUM * B_MAX];
__device__ float g_gate[E_NUM * B_MAX];
// 2*B_MAX rows of H_DIM fp32 = 64 MB
__device__ float g_hbuf[(size_t)2 * B_MAX * H_DIM];

// ---------------- init: zero moe-out region + counters ----------------
__global__ void init_kernel(float* __restrict__ out, long n)
{
    long i = (long)blockIdx.x * blockDim.x + threadIdx.x;
    long stride = (long)gridDim.x * blockDim.x;
    for (; i < n; i += stride) out[i] = 0.0f;
    if (blockIdx.x == 0 && threadIdx.x < E_NUM) g_counts[threadIdx.x] = 0;
}

// ---------------- gating: one warp per token ----------------
__global__ void gating_kernel(const float* __restrict__ x,
                              const float* __restrict__ noise,
                              const float* __restrict__ Wg, const float* __restrict__ bg,
                              const float* __restrict__ Wn, const float* __restrict__ bn,
                              float* __restrict__ out_clean,
                              float* __restrict__ out_idx,
                              int B)
{
    int warp = threadIdx.x >> 5;
    int lane = threadIdx.x & 31;
    int tok  = blockIdx.x * 8 + warp;
    if (tok >= B) return;

    const float* xr = x + (size_t)tok * D_DIM;
    float cg[E_NUM] = {}, cn[E_NUM] = {};
    for (int d = lane; d < D_DIM; d += 32) {
        float xv = __ldg(xr + d);
        const float4* wg = (const float4*)(Wg + d * E_NUM);
        const float4* wn = (const float4*)(Wn + d * E_NUM);
        float4 a = wg[0], b = wg[1], c = wn[0], e4 = wn[1];
        cg[0] += xv * a.x;  cg[1] += xv * a.y;  cg[2] += xv * a.z;  cg[3] += xv * a.w;
        cg[4] += xv * b.x;  cg[5] += xv * b.y;  cg[6] += xv * b.z;  cg[7] += xv * b.w;
        cn[0] += xv * c.x;  cn[1] += xv * c.y;  cn[2] += xv * c.z;  cn[3] += xv * c.w;
        cn[4] += xv * e4.x; cn[5] += xv * e4.y; cn[6] += xv * e4.z; cn[7] += xv * e4.w;
    }
    #pragma unroll
    for (int off = 16; off > 0; off >>= 1) {
        #pragma unroll
        for (int e = 0; e < E_NUM; e++) {
            cg[e] += __shfl_xor_sync(0xffffffff, cg[e], off);
            cn[e] += __shfl_xor_sync(0xffffffff, cn[e], off);
        }
    }
    if (lane == 0) {
        float noisy[E_NUM];
        #pragma unroll
        for (int e = 0; e < E_NUM; e++) {
            float clean = cg[e] + bg[e];
            float z = cn[e] + bn[e];
            // numerically stable softplus, matches jax.nn.softplus in fp32
            float sp = (z > 0.0f) ? z + log1pf(expf(-z)) : log1pf(expf(z));
            noisy[e] = clean + noise[(size_t)tok * E_NUM + e] * sp;
            out_clean[(size_t)tok * E_NUM + e] = clean;
        }
        // top-2 with jax tie-breaking (first occurrence of max wins)
        int i0 = 0;
        #pragma unroll
        for (int e = 1; e < E_NUM; e++) if (noisy[e] > noisy[i0]) i0 = e;
        int i1 = (i0 == 0) ? 1 : 0;
        #pragma unroll
        for (int e = 0; e < E_NUM; e++)
            if (e != i0 && noisy[e] > noisy[i1]) i1 = e;

        float v0 = noisy[i0], v1 = noisy[i1];
        float e1 = expf(v1 - v0);
        float w0 = 1.0f / (1.0f + e1);
        float w1 = e1 / (1.0f + e1);

        out_idx[(size_t)tok * 2 + 0] = (float)i0;
        out_idx[(size_t)tok * 2 + 1] = (float)i1;

        int p0 = atomicAdd(&g_counts[i0], 1);
        g_tok [i0 * B_MAX + p0] = tok;
        g_gate[i0 * B_MAX + p0] = w0;
        int p1 = atomicAdd(&g_counts[i1], 1);
        g_tok [i1 * B_MAX + p1] = tok;
        g_gate[i1 * B_MAX + p1] = w1;
    }
}

// ---------------- tiny prefix scan over 8 experts ----------------
__global__ void scan_kernel()
{
    if (threadIdx.x == 0) {
        int s = 0;
        for (int e = 0; e < E_NUM; e++) { g_base[e] = s; s += g_counts[e]; }
        g_base[E_NUM] = s;
    }
}

// ---------------- grouped GEMM1: h = gather(x) @ W1[e] + b1[e] ----------------
// 128x128 tile, K-step 8, 256 threads, 8x8 per-thread microtile,
// software-pipelined (next K-slab loaded to regs during compute).
__global__ __launch_bounds__(256, 2)
void gemm1_kernel(const float* __restrict__ x, const float* __restrict__ W1,
                  const float* __restrict__ b1)
{
    int e   = blockIdx.z;
    int cnt = g_counts[e];
    int m0  = blockIdx.y * 128;
    if (m0 >= cnt) return;
    int n0   = blockIdx.x * 128;
    int base = g_base[e];

    __shared__ float As[8][128];
    __shared__ float Bs[8][128];

    int t  = threadIdx.x;
    int tx = t & 15, ty = t >> 4;
    float acc[8][8] = {};

    int lrow  = t >> 1;
    int lhalf = (t & 1) * 4;
    int mi    = min(m0 + lrow, cnt - 1);
    int atok  = g_tok[e * B_MAX + mi];
    const float* aptr = x + (size_t)atok * D_DIM + lhalf;

    int bk = t >> 5;
    int bn = (t & 31) * 4;
    const float* bptr = W1 + ((size_t)e * D_DIM + bk) * H_DIM + n0 + bn;

    float4 av = *(const float4*)(aptr);
    float4 bv = *(const float4*)(bptr);

    for (int k0 = 0; k0 < D_DIM; k0 += 8) {
        As[lhalf + 0][lrow] = av.x; As[lhalf + 1][lrow] = av.y;
        As[lhalf + 2][lrow] = av.z; As[lhalf + 3][lrow] = av.w;
        *(float4*)&Bs[bk][bn] = bv;
        __syncthreads();

        int kn = k0 + 8;
        if (kn < D_DIM) {
            av = *(const float4*)(aptr + kn);
            bv = *(const float4*)(bptr + (size_t)kn * H_DIM);
        }

        #pragma unroll
        for (int kk = 0; kk < 8; kk++) {
            float a[8], b[8];
            *(float4*)(a)     = *(const float4*)&As[kk][ty * 8];
            *(float4*)(a + 4) = *(const float4*)&As[kk][ty * 8 + 4];
            *(float4*)(b)     = *(const float4*)&Bs[kk][tx * 8];
            *(float4*)(b + 4) = *(const float4*)&Bs[kk][tx * 8 + 4];
            #pragma unroll
            for (int i = 0; i < 8; i++)
                #pragma unroll
                for (int j = 0; j < 8; j++)
                    acc[i][j] += a[i] * b[j];
        }
        __syncthreads();
    }

    #pragma unroll
    for (int i = 0; i < 8; i++) {
        int m = m0 + ty * 8 + i;
        if (m < cnt) {
            float* hrow = g_hbuf + (size_t)(base + m) * H_DIM + n0 + tx * 8;
            const float* brow = b1 + (size_t)e * H_DIM + n0 + tx * 8;
            #pragma unroll
            for (int j = 0; j < 8; j++) hrow[j] = acc[i][j] + brow[j];
        }
    }
}

// ---------------- LayerNorm + exact GELU, one block per slot row ----------------
__global__ void ln_gelu_kernel(const float* __restrict__ ln_g,
                               const float* __restrict__ ln_b)
{
    int r = blockIdx.x;
    int e = 0;
    #pragma unroll
    for (int k = 1; k < E_NUM; k++) if (r >= g_base[k]) e = k;

    float* row = g_hbuf + (size_t)r * H_DIM;
    int t = threadIdx.x;                 // 256 threads, 4 floats each
    float4 v = *(float4*)(row + t * 4);
    float s  = v.x + v.y + v.z + v.w;
    float sq = v.x * v.x + v.y * v.y + v.z * v.z + v.w * v.w;

    __shared__ float ssum[8], ssq[8];
    int lane = t & 31, wid = t >> 5;
    #pragma unroll
    for (int off = 16; off > 0; off >>= 1) {
        s  += __shfl_xor_sync(0xffffffff, s,  off);
        sq += __shfl_xor_sync(0xffffffff, sq, off);
    }
    if (lane == 0) { ssum[wid] = s; ssq[wid] = sq; }
    __syncthreads();
    float S = 0.0f, SQ = 0.0f;
    #pragma unroll
    for (int w = 0; w < 8; w++) { S += ssum[w]; SQ += ssq[w]; }

    float mean = S * (1.0f / H_DIM);
    float var  = SQ * (1.0f / H_DIM) - mean * mean;
    float inv  = 1.0f / sqrtf(var + 1e-5f);

    const float4 g4 = *(const float4*)(ln_g + (size_t)e * H_DIM + t * 4);
    const float4 b4 = *(const float4*)(ln_b + (size_t)e * H_DIM + t * 4);

    float u;
    u = (v.x - mean) * inv * g4.x + b4.x; v.x = 0.5f * u * (1.0f + erff(u * 0.7071067811865475f));
    u = (v.y - mean) * inv * g4.y + b4.y; v.y = 0.5f * u * (1.0f + erff(u * 0.7071067811865475f));
    u = (v.z - mean) * inv * g4.z + b4.z; v.z = 0.5f * u * (1.0f + erff(u * 0.7071067811865475f));
    u = (v.w - mean) * inv * g4.w + b4.w; v.w = 0.5f * u * (1.0f + erff(u * 0.7071067811865475f));

    *(float4*)(row + t * 4) = v;
}

// ---------------- grouped GEMM2: out += gate * (h @ W2[e] + b2[e]) ----------------
__global__ __launch_bounds__(256, 2)
void gemm2_kernel(const float* __restrict__ W2, const float* __restrict__ b2,
                  float* __restrict__ out)
{
    int e   = blockIdx.z;
    int cnt = g_counts[e];
    int m0  = blockIdx.y * 128;
    if (m0 >= cnt) return;
    int n0   = blockIdx.x * 128;
    int base = g_base[e];

    __shared__ float As[8][128];
    __shared__ float Bs[8][128];

    int t  = threadIdx.x;
    int tx = t & 15, ty = t >> 4;
    float acc[8][8] = {};

    int lrow  = t >> 1;
    int lhalf = (t & 1) * 4;
    int mi    = min(m0 + lrow, cnt - 1);
    const float* aptr = g_hbuf + (size_t)(base + mi) * H_DIM + lhalf;

    int bk = t >> 5;
    int bn = (t & 31) * 4;
    const float* bptr = W2 + ((size_t)e * H_DIM + bk) * D_DIM + n0 + bn;

    float4 av = *(const float4*)(aptr);
    float4 bv = *(const float4*)(bptr);

    for (int k0 = 0; k0 < H_DIM; k0 += 8) {
        As[lhalf + 0][lrow] = av.x; As[lhalf + 1][lrow] = av.y;
        As[lhalf + 2][lrow] = av.z; As[lhalf + 3][lrow] = av.w;
        *(float4*)&Bs[bk][bn] = bv;
        __syncthreads();

        int kn = k0 + 8;
        if (kn < H_DIM) {
            av = *(const float4*)(aptr + kn);
            bv = *(const float4*)(bptr + (size_t)kn * D_DIM);
        }

        #pragma unroll
        for (int kk = 0; kk < 8; kk++) {
            float a[8], b[8];
            *(float4*)(a)     = *(const float4*)&As[kk][ty * 8];
            *(float4*)(a + 4) = *(const float4*)&As[kk][ty * 8 + 4];
            *(float4*)(b)     = *(const float4*)&Bs[kk][tx * 8];
            *(float4*)(b + 4) = *(const float4*)&Bs[kk][tx * 8 + 4];
            #pragma unroll
            for (int i = 0; i < 8; i++)
                #pragma unroll
                for (int j = 0; j < 8; j++)
                    acc[i][j] += a[i] * b[j];
        }
        __syncthreads();
    }

    #pragma unroll
    for (int i = 0; i < 8; i++) {
        int m = m0 + ty * 8 + i;
        if (m < cnt) {
            int   tokm = g_tok [e * B_MAX + m];
            float gw   = g_gate[e * B_MAX + m];
            float* orow = out + (size_t)tokm * D_DIM + n0 + tx * 8;
            const float* brow = b2 + (size_t)e * D_DIM + n0 + tx * 8;
            #pragma unroll
            for (int j = 0; j < 8; j++)
                atomicAdd(orow + j, (acc[i][j] + brow[j]) * gw);
        }
    }
}

// ---------------- launch ----------------
extern "C" void kernel_launch(void* const* d_in, const int* in_sizes, int n_in,
                              void* d_out, int out_size)
{
    const float* x     = (const float*)d_in[0];
    const float* noise = (const float*)d_in[1];
    const float* Wg    = (const float*)d_in[2];
    const float* bg    = (const float*)d_in[3];
    const float* Wn    = (const float*)d_in[4];
    const float* bn    = (const float*)d_in[5];
    const float* W1    = (const float*)d_in[6];
    const float* b1    = (const float*)d_in[7];
    const float* lng   = (const float*)d_in[8];
    const float* lnb   = (const float*)d_in[9];
    const float* W2    = (const float*)d_in[10];
    const float* b2    = (const float*)d_in[11];

    float* out = (float*)d_out;
    int B = in_sizes[0] / D_DIM;                     // 8192

    float* out_clean = out + (size_t)B * D_DIM;      // [B, E]
    float* out_idx   = out_clean + (size_t)B * E_NUM; // [B, 2] as float

    init_kernel<<<1024, 256>>>(out, (long)B * D_DIM);
    gating_kernel<<<(B + 7) / 8, 256>>>(x, noise, Wg, bg, Wn, bn, out_clean, out_idx, B);
    scan_kernel<<<1, 32>>>();

    dim3 g1(H_DIM / 128, (B + 127) / 128, E_NUM);
    gemm1_kernel<<<g1, 256>>>(x, W1, b1);

    ln_gelu_kernel<<<2 * B, 256>>>(lng, lnb);

    dim3 g2(D_DIM / 128, (B + 127) / 128, E_NUM);
    gemm2_kernel<<<g2, 256>>>(W2, b2, out);
}

// round 4
// speedup vs baseline: 2.1926x; 2.1926x over previous
#include <cuda_runtime.h>
#include <math.h>
#include <stdint.h>

#define D_DIM 768
#define H_DIM 1024
#define E_NUM 8
#define B_MAX 8192
#define NSLOT (2 * B_MAX)

// ---------------- scratch (device globals; no allocations) ----------------
__device__ int   g_counts[E_NUM];
__device__ int   g_base[E_NUM + 1];
__device__ int   g_tok [E_NUM * B_MAX];
__device__ float g_gate[E_NUM * B_MAX];
__device__ int   g_pos [2 * B_MAX];               // per token: e*B_MAX + p
__device__ float g_hbuf[(size_t)NSLOT * H_DIM];   // 64 MB
__device__ float g_obuf[(size_t)NSLOT * D_DIM];   // 50 MB

// ---------------- helpers ----------------
__device__ __forceinline__ uint32_t pack_bf16(float lo_elem, float hi_elem) {
    // result: low 16 bits = bf16(lo_elem) [element k], high = bf16(hi_elem) [element k+1]
    uint32_t r;
    asm("cvt.rn.bf16x2.f32 %0, %1, %2;" : "=r"(r) : "f"(hi_elem), "f"(lo_elem));
    return r;
}
__device__ __forceinline__ float2 unpack_bf16(uint32_t w) {
    float2 r;
    r.x = __uint_as_float(w << 16);          // low half
    r.y = __uint_as_float(w & 0xffff0000u);  // high half
    return r;
}
__device__ __forceinline__ void mma_bf16(float* d, const uint32_t* a, const uint32_t* b) {
    asm volatile(
        "mma.sync.aligned.m16n8k16.row.col.f32.bf16.bf16.f32 "
        "{%0,%1,%2,%3}, {%4,%5,%6,%7}, {%8,%9}, {%0,%1,%2,%3};"
        : "+f"(d[0]), "+f"(d[1]), "+f"(d[2]), "+f"(d[3])
        : "r"(a[0]), "r"(a[1]), "r"(a[2]), "r"(a[3]), "r"(b[0]), "r"(b[1]));
}

// ---------------- zero counters ----------------
__global__ void zero_counters_kernel() {
    if (threadIdx.x < E_NUM) g_counts[threadIdx.x] = 0;
}

// ---------------- gating: one warp per token (exact fp32) ----------------
__global__ void gating_kernel(const float* __restrict__ x,
                              const float* __restrict__ noise,
                              const float* __restrict__ Wg, const float* __restrict__ bg,
                              const float* __restrict__ Wn, const float* __restrict__ bn,
                              float* __restrict__ out_clean,
                              float* __restrict__ out_idx,
                              int B)
{
    int warp = threadIdx.x >> 5;
    int lane = threadIdx.x & 31;
    int tok  = blockIdx.x * 8 + warp;
    if (tok >= B) return;

    const float* xr = x + (size_t)tok * D_DIM;
    float cg[E_NUM] = {}, cn[E_NUM] = {};
    for (int d = lane; d < D_DIM; d += 32) {
        float xv = __ldg(xr + d);
        const float4* wg = (const float4*)(Wg + d * E_NUM);
        const float4* wn = (const float4*)(Wn + d * E_NUM);
        float4 a = wg[0], b = wg[1], c = wn[0], e4 = wn[1];
        cg[0] += xv * a.x;  cg[1] += xv * a.y;  cg[2] += xv * a.z;  cg[3] += xv * a.w;
        cg[4] += xv * b.x;  cg[5] += xv * b.y;  cg[6] += xv * b.z;  cg[7] += xv * b.w;
        cn[0] += xv * c.x;  cn[1] += xv * c.y;  cn[2] += xv * c.z;  cn[3] += xv * c.w;
        cn[4] += xv * e4.x; cn[5] += xv * e4.y; cn[6] += xv * e4.z; cn[7] += xv * e4.w;
    }
    #pragma unroll
    for (int off = 16; off > 0; off >>= 1) {
        #pragma unroll
        for (int e = 0; e < E_NUM; e++) {
            cg[e] += __shfl_xor_sync(0xffffffff, cg[e], off);
            cn[e] += __shfl_xor_sync(0xffffffff, cn[e], off);
        }
    }
    if (lane == 0) {
        float noisy[E_NUM];
        #pragma unroll
        for (int e = 0; e < E_NUM; e++) {
            float clean = cg[e] + bg[e];
            float z = cn[e] + bn[e];
            float sp = (z > 0.0f) ? z + log1pf(expf(-z)) : log1pf(expf(z));
            noisy[e] = clean + noise[(size_t)tok * E_NUM + e] * sp;
            out_clean[(size_t)tok * E_NUM + e] = clean;
        }
        int i0 = 0;
        #pragma unroll
        for (int e = 1; e < E_NUM; e++) if (noisy[e] > noisy[i0]) i0 = e;
        int i1 = (i0 == 0) ? 1 : 0;
        #pragma unroll
        for (int e = 0; e < E_NUM; e++)
            if (e != i0 && noisy[e] > noisy[i1]) i1 = e;

        float v0 = noisy[i0], v1 = noisy[i1];
        float e1 = expf(v1 - v0);
        float w0 = 1.0f / (1.0f + e1);
        float w1 = e1 / (1.0f + e1);

        out_idx[(size_t)tok * 2 + 0] = (float)i0;
        out_idx[(size_t)tok * 2 + 1] = (float)i1;

        int p0 = atomicAdd(&g_counts[i0], 1);
        g_tok [i0 * B_MAX + p0] = tok;
        g_gate[i0 * B_MAX + p0] = w0;
        g_pos [tok * 2 + 0] = i0 * B_MAX + p0;
        int p1 = atomicAdd(&g_counts[i1], 1);
        g_tok [i1 * B_MAX + p1] = tok;
        g_gate[i1 * B_MAX + p1] = w1;
        g_pos [tok * 2 + 1] = i1 * B_MAX + p1;
    }
}

// ---------------- prefix scan over 8 experts ----------------
__global__ void scan_kernel() {
    if (threadIdx.x == 0) {
        int s = 0;
        for (int e = 0; e < E_NUM; e++) { g_base[e] = s; s += g_counts[e]; }
        g_base[E_NUM] = s;
    }
}

// =====================================================================
// Tensor-core grouped GEMM via mma.sync bf16, 3-pass split compensation.
// CTA tile 128(M) x 128(N), k-slab 16. 8 warps: 2(M) x 4(N), warp 64x32.
// SMEM layout [k2][row] padded to 136 words -> conflict-free fragment LDS.
// GATHER=1: A rows gathered via s_tok (gemm1). SCALE=1: epilogue *gate (gemm2).
// =====================================================================
#define PAD 136

struct GemmSmem {
    uint32_t A[2][2][8][PAD];   // [stage][hi/lo][k2][m]
    uint32_t Bm[2][2][8][PAD];  // [stage][hi/lo][k2][n]
    int      tok[128];
    float    gate[128];
};

template<int KDIM, int NDIM, bool GATHER, bool SCALE>
__global__ __launch_bounds__(256, 2)
void gemm_tc_kernel(const float* __restrict__ Asrc,   // x (gemm1) or g_hbuf (gemm2)
                    const float* __restrict__ W,      // W1 or W2 ([e][K][N])
                    const float* __restrict__ bias,   // b1 or b2 ([e][N])
                    float* __restrict__ Out,          // g_hbuf or g_obuf
                    int out_stride)
{
    int e   = blockIdx.z;
    int cnt = g_counts[e];
    int m0  = blockIdx.y * 128;
    if (m0 >= cnt) return;
    int n0g   = blockIdx.x * 128;
    int gbase = g_base[e];

    __shared__ GemmSmem sm;

    int t    = threadIdx.x;
    int lane = t & 31;
    int w    = t >> 5;
    int wm   = (w >> 2) * 64;     // warp M offset
    int wn   = (w & 3) * 32;      // warp N offset
    int g    = lane >> 2;
    int tt   = lane & 3;

    for (int i = t; i < 128; i += 256) {
        int mi = min(m0 + i, cnt - 1);
        if (GATHER) sm.tok[i] = g_tok[e * B_MAX + mi];
        if (SCALE)  sm.gate[i] = g_gate[e * B_MAX + mi];
    }
    __syncthreads();

    // ---- per-thread global load assignments ----
    // A: 4 x (m, k2): idx = t + r*256 ; m = idx>>3, k2 = idx&7 (float2 loads)
    const float* aptr[4];
    int am[4], ak2[4];
    #pragma unroll
    for (int r = 0; r < 4; r++) {
        int idx = t + r * 256;
        am[r]  = idx >> 3;
        ak2[r] = idx & 7;
        int row;
        if (GATHER) row = sm.tok[am[r]];
        else        row = gbase + min(m0 + am[r], cnt - 1);
        aptr[r] = Asrc + (size_t)row * KDIM + 2 * ak2[r];
    }
    // B: k2 = t>>5, n-quad = (t&31)*4 ; two LDG.128 per slab
    int bk2 = t >> 5;
    int bnq = (t & 31) * 4;
    const float* bptr0 = W + ((size_t)e * KDIM + 2 * bk2)     * NDIM + n0g + bnq;
    const float* bptr1 = W + ((size_t)e * KDIM + 2 * bk2 + 1) * NDIM + n0g + bnq;

    float acc[4][4][4] = {};

    const int S = KDIM / 16;

    // prolog: load slab 0
    float2 aval[4];
    float4 bv0, bv1;
    #pragma unroll
    for (int r = 0; r < 4; r++) aval[r] = *(const float2*)(aptr[r]);
    bv0 = *(const float4*)(bptr0);
    bv1 = *(const float4*)(bptr1);

    for (int s = 0; s < S; s++) {
        int p = s & 1;
        // convert + STS current slab
        #pragma unroll
        for (int r = 0; r < 4; r++) {
            uint32_t hi = pack_bf16(aval[r].x, aval[r].y);
            float2 h = unpack_bf16(hi);
            uint32_t lo = pack_bf16(aval[r].x - h.x, aval[r].y - h.y);
            sm.A[p][0][ak2[r]][am[r]] = hi;
            sm.A[p][1][ak2[r]][am[r]] = lo;
        }
        {
            uint32_t hi4[4], lo4[4];
            const float* f0 = (const float*)&bv0;
            const float* f1 = (const float*)&bv1;
            #pragma unroll
            for (int c = 0; c < 4; c++) {
                hi4[c] = pack_bf16(f0[c], f1[c]);
                float2 h = unpack_bf16(hi4[c]);
                lo4[c] = pack_bf16(f0[c] - h.x, f1[c] - h.y);
            }
            *(uint4*)&sm.Bm[p][0][bk2][bnq] = *(uint4*)hi4;
            *(uint4*)&sm.Bm[p][1][bk2][bnq] = *(uint4*)lo4;
        }
        __syncthreads();

        // prefetch next slab into registers
        if (s + 1 < S) {
            int k0 = (s + 1) * 16;
            #pragma unroll
            for (int r = 0; r < 4; r++) aval[r] = *(const float2*)(aptr[r] + k0);
            bv0 = *(const float4*)(bptr0 + (size_t)k0 * NDIM);
            bv1 = *(const float4*)(bptr1 + (size_t)k0 * NDIM);
        }

        // compute: 3 passes (AhiBhi, AhiBlo, AloBhi)
        #pragma unroll
        for (int pass = 0; pass < 3; pass++) {
            const uint32_t (*pA)[PAD] = sm.A[p][pass == 2 ? 1 : 0];
            const uint32_t (*pB)[PAD] = sm.Bm[p][pass == 1 ? 1 : 0];
            uint32_t af[4][4], bf_[4][2];
            #pragma unroll
            for (int i = 0; i < 4; i++) {
                int mt = wm + i * 16;
                af[i][0] = pA[tt][mt + g];
                af[i][1] = pA[tt][mt + g + 8];
                af[i][2] = pA[tt + 4][mt + g];
                af[i][3] = pA[tt + 4][mt + g + 8];
            }
            #pragma unroll
            for (int j = 0; j < 4; j++) {
                int nt = wn + j * 8;
                bf_[j][0] = pB[tt][nt + g];
                bf_[j][1] = pB[tt + 4][nt + g];
            }
            #pragma unroll
            for (int i = 0; i < 4; i++)
                #pragma unroll
                for (int j = 0; j < 4; j++)
                    mma_bf16(acc[i][j], af[i], bf_[j]);
        }
        __syncthreads();
    }

    // ---- epilogue ----
    const float* brow = bias + (size_t)e * NDIM + n0g;
    #pragma unroll
    for (int i = 0; i < 4; i++) {
        #pragma unroll
        for (int f = 0; f < 2; f++) {
            int rloc = wm + i * 16 + g + f * 8;
            int m = m0 + rloc;
            if (m < cnt) {
                float gw = SCALE ? sm.gate[rloc] : 1.0f;
                float* orow = Out + (size_t)(gbase + m) * out_stride + n0g;
                #pragma unroll
                for (int j = 0; j < 4; j++) {
                    int col = wn + j * 8 + tt * 2;
                    float2 o;
                    o.x = acc[i][j][f * 2 + 0] + __ldg(brow + col);
                    o.y = acc[i][j][f * 2 + 1] + __ldg(brow + col + 1);
                    if (SCALE) { o.x *= gw; o.y *= gw; }
                    *(float2*)(orow + col) = o;
                }
            }
        }
    }
}

// ---------------- LayerNorm + exact GELU, one block per slot row ----------------
__global__ void ln_gelu_kernel(const float* __restrict__ ln_g,
                               const float* __restrict__ ln_b)
{
    int r = blockIdx.x;
    int e = 0;
    #pragma unroll
    for (int k = 1; k < E_NUM; k++) if (r >= g_base[k]) e = k;

    float* row = g_hbuf + (size_t)r * H_DIM;
    int t = threadIdx.x;
    float4 v = *(float4*)(row + t * 4);
    float s  = v.x + v.y + v.z + v.w;
    float sq = v.x * v.x + v.y * v.y + v.z * v.z + v.w * v.w;

    __shared__ float ssum[8], ssq[8];
    int lane = t & 31, wid = t >> 5;
    #pragma unroll
    for (int off = 16; off > 0; off >>= 1) {
        s  += __shfl_xor_sync(0xffffffff, s,  off);
        sq += __shfl_xor_sync(0xffffffff, sq, off);
    }
    if (lane == 0) { ssum[wid] = s; ssq[wid] = sq; }
    __syncthreads();
    float S = 0.0f, SQ = 0.0f;
    #pragma unroll
    for (int w = 0; w < 8; w++) { S += ssum[w]; SQ += ssq[w]; }

    float mean = S * (1.0f / H_DIM);
    float var  = SQ * (1.0f / H_DIM) - mean * mean;
    float inv  = 1.0f / sqrtf(var + 1e-5f);

    const float4 g4 = *(const float4*)(ln_g + (size_t)e * H_DIM + t * 4);
    const float4 b4 = *(const float4*)(ln_b + (size_t)e * H_DIM + t * 4);

    float u;
    u = (v.x - mean) * inv * g4.x + b4.x; v.x = 0.5f * u * (1.0f + erff(u * 0.7071067811865475f));
    u = (v.y - mean) * inv * g4.y + b4.y; v.y = 0.5f * u * (1.0f + erff(u * 0.7071067811865475f));
    u = (v.z - mean) * inv * g4.z + b4.z; v.z = 0.5f * u * (1.0f + erff(u * 0.7071067811865475f));
    u = (v.w - mean) * inv * g4.w + b4.w; v.w = 0.5f * u * (1.0f + erff(u * 0.7071067811865475f));

    *(float4*)(row + t * 4) = v;
}

// ---------------- combine: out[tok] = obuf[slot0] + obuf[slot1] ----------------
__global__ void combine_kernel(float* __restrict__ out)
{
    int tok = blockIdx.x;
    int enc0 = g_pos[tok * 2], enc1 = g_pos[tok * 2 + 1];
    int s0 = g_base[enc0 >> 13] + (enc0 & (B_MAX - 1));
    int s1 = g_base[enc1 >> 13] + (enc1 & (B_MAX - 1));
    const float4* r0 = (const float4*)(g_obuf + (size_t)s0 * D_DIM);
    const float4* r1 = (const float4*)(g_obuf + (size_t)s1 * D_DIM);
    float4* o = (float4*)(out + (size_t)tok * D_DIM);
    int i = threadIdx.x;                 // 192 threads
    float4 a = r0[i], b = r1[i];
    o[i] = make_float4(a.x + b.x, a.y + b.y, a.z + b.z, a.w + b.w);
}

// ---------------- launch ----------------
extern "C" void kernel_launch(void* const* d_in, const int* in_sizes, int n_in,
                              void* d_out, int out_size)
{
    const float* x     = (const float*)d_in[0];
    const float* noise = (const float*)d_in[1];
    const float* Wg    = (const float*)d_in[2];
    const float* bg    = (const float*)d_in[3];
    const float* Wn    = (const float*)d_in[4];
    const float* bn    = (const float*)d_in[5];
    const float* W1    = (const float*)d_in[6];
    const float* b1    = (const float*)d_in[7];
    const float* lng   = (const float*)d_in[8];
    const float* lnb   = (const float*)d_in[9];
    const float* W2    = (const float*)d_in[10];
    const float* b2    = (const float*)d_in[11];

    float* out = (float*)d_out;
    int B = in_sizes[0] / D_DIM;                      // 8192

    float* out_clean = out + (size_t)B * D_DIM;       // [B, E]
    float* out_idx   = out_clean + (size_t)B * E_NUM; // [B, 2] as float

    float* hbuf; cudaGetSymbolAddress((void**)&hbuf, g_hbuf);
    float* obuf; cudaGetSymbolAddress((void**)&obuf, g_obuf);

    zero_counters_kernel<<<1, 32>>>();
    gating_kernel<<<(B + 7) / 8, 256>>>(x, noise, Wg, bg, Wn, bn, out_clean, out_idx, B);
    scan_kernel<<<1, 32>>>();

    // gemm1: h = gather(x) @ W1[e] + b1  (M up to cnt, N=1024, K=768)
    gemm_tc_kernel<D_DIM, H_DIM, true, false>
        <<<dim3(H_DIM / 128, B_MAX / 128, E_NUM), 256>>>(x, W1, b1, hbuf, H_DIM);

    ln_gelu_kernel<<<2 * B, 256>>>(lng, lnb);

    // gemm2: obuf = gate * (h @ W2[e] + b2)  (N=768, K=1024)
    gemm_tc_kernel<H_DIM, D_DIM, false, true>
        <<<dim3(D_DIM / 128, B_MAX / 128, E_NUM), 256>>>(hbuf, W2, b2, obuf, D_DIM);

    combine_kernel<<<B, 192>>>(out);
}

// round 5
// speedup vs baseline: 2.4039x; 1.0963x over previous
#include <cuda_runtime.h>
#include <cuda_bf16.h>
#include <math.h>
#include <stdint.h>

#define D_DIM 768
#define H_DIM 1024
#define E_NUM 8
#define B_MAX 8192
#define NSLOT (2 * B_MAX)

// ---------------- scratch (device globals; no allocations) ----------------
__device__ int   g_counts[E_NUM];
__device__ int   g_base[E_NUM + 1];
__device__ int   g_tok [E_NUM * B_MAX];
__device__ float g_gate[E_NUM * B_MAX];
__device__ int   g_pos [2 * B_MAX];
__device__ float g_hbuf[(size_t)NSLOT * H_DIM];   // 64 MB fp32 h
__device__ float g_obuf[(size_t)NSLOT * D_DIM];   // 50 MB fp32 per-slot out
// pre-split bf16 hi/lo operands
__device__ __nv_bfloat16 g_xs_hi[(size_t)B_MAX * D_DIM];
__device__ __nv_bfloat16 g_xs_lo[(size_t)B_MAX * D_DIM];
__device__ __nv_bfloat16 g_w1_hi[(size_t)E_NUM * D_DIM * H_DIM];
__device__ __nv_bfloat16 g_w1_lo[(size_t)E_NUM * D_DIM * H_DIM];
__device__ __nv_bfloat16 g_w2_hi[(size_t)E_NUM * H_DIM * D_DIM];
__device__ __nv_bfloat16 g_w2_lo[(size_t)E_NUM * H_DIM * D_DIM];
__device__ __nv_bfloat16 g_hs_hi[(size_t)NSLOT * H_DIM];
__device__ __nv_bfloat16 g_hs_lo[(size_t)NSLOT * H_DIM];

// ---------------- helpers ----------------
__device__ __forceinline__ uint32_t smem_u32(const void* p) {
    uint32_t a;
    asm("{ .reg .u64 t; cvta.to.shared.u64 t, %1; cvt.u32.u64 %0, t; }" : "=r"(a) : "l"(p));
    return a;
}
__device__ __forceinline__ uint32_t pack_bf16(float lo_elem, float hi_elem) {
    uint32_t r;
    asm("cvt.rn.bf16x2.f32 %0, %1, %2;" : "=r"(r) : "f"(hi_elem), "f"(lo_elem));
    return r;
}
__device__ __forceinline__ float2 unpack_bf16(uint32_t w) {
    float2 r;
    r.x = __uint_as_float(w << 16);
    r.y = __uint_as_float(w & 0xffff0000u);
    return r;
}
__device__ __forceinline__ void mma_bf16(float* d, const uint32_t* a, const uint32_t* b) {
    asm volatile(
        "mma.sync.aligned.m16n8k16.row.col.f32.bf16.bf16.f32 "
        "{%0,%1,%2,%3}, {%4,%5,%6,%7}, {%8,%9}, {%0,%1,%2,%3};"
        : "+f"(d[0]), "+f"(d[1]), "+f"(d[2]), "+f"(d[3])
        : "r"(a[0]), "r"(a[1]), "r"(a[2]), "r"(a[3]), "r"(b[0]), "r"(b[1]));
}
#define LDSM4(r, addr) \
    asm volatile("ldmatrix.sync.aligned.m8n8.x4.shared.b16 {%0,%1,%2,%3}, [%4];" \
        : "=r"((r)[0]), "=r"((r)[1]), "=r"((r)[2]), "=r"((r)[3]) : "r"(addr))
#define LDSM4T(r, addr) \
    asm volatile("ldmatrix.sync.aligned.m8n8.x4.trans.shared.b16 {%0,%1,%2,%3}, [%4];" \
        : "=r"((r)[0]), "=r"((r)[1]), "=r"((r)[2]), "=r"((r)[3]) : "r"(addr))
#define CP16(dst, src) \
    asm volatile("cp.async.cg.shared.global [%0], [%1], 16;" :: "r"(dst), "l"(src))
#define CPCOMMIT() asm volatile("cp.async.commit_group;" ::: "memory")
#define CPWAIT1()  asm volatile("cp.async.wait_group 1;" ::: "memory")

// ---------------- zero counters ----------------
__global__ void zero_counters_kernel() {
    if (threadIdx.x < E_NUM) g_counts[threadIdx.x] = 0;
}

// ---------------- split fp32 -> bf16 hi/lo ----------------
__global__ void split_kernel(const float* __restrict__ in,
                             __nv_bfloat16* __restrict__ hi,
                             __nv_bfloat16* __restrict__ lo, int n4)
{
    int i = blockIdx.x * blockDim.x + threadIdx.x;
    if (i >= n4) return;
    float4 v = ((const float4*)in)[i];
    uint32_t h0 = pack_bf16(v.x, v.y), h1 = pack_bf16(v.z, v.w);
    float2 f0 = unpack_bf16(h0), f1 = unpack_bf16(h1);
    uint32_t l0 = pack_bf16(v.x - f0.x, v.y - f0.y);
    uint32_t l1 = pack_bf16(v.z - f1.x, v.w - f1.y);
    ((uint2*)hi)[i] = make_uint2(h0, h1);
    ((uint2*)lo)[i] = make_uint2(l0, l1);
}

// ---------------- gating: one warp per token (exact fp32) ----------------
__global__ void gating_kernel(const float* __restrict__ x,
                              const float* __restrict__ noise,
                              const float* __restrict__ Wg, const float* __restrict__ bg,
                              const float* __restrict__ Wn, const float* __restrict__ bn,
                              float* __restrict__ out_clean,
                              float* __restrict__ out_idx,
                              int B)
{
    int warp = threadIdx.x >> 5;
    int lane = threadIdx.x & 31;
    int tok  = blockIdx.x * 8 + warp;
    if (tok >= B) return;

    const float* xr = x + (size_t)tok * D_DIM;
    float cg[E_NUM] = {}, cn[E_NUM] = {};
    for (int d = lane; d < D_DIM; d += 32) {
        float xv = __ldg(xr + d);
        const float4* wg = (const float4*)(Wg + d * E_NUM);
        const float4* wn = (const float4*)(Wn + d * E_NUM);
        float4 a = wg[0], b = wg[1], c = wn[0], e4 = wn[1];
        cg[0] += xv * a.x;  cg[1] += xv * a.y;  cg[2] += xv * a.z;  cg[3] += xv * a.w;
        cg[4] += xv * b.x;  cg[5] += xv * b.y;  cg[6] += xv * b.z;  cg[7] += xv * b.w;
        cn[0] += xv * c.x;  cn[1] += xv * c.y;  cn[2] += xv * c.z;  cn[3] += xv * c.w;
        cn[4] += xv * e4.x; cn[5] += xv * e4.y; cn[6] += xv * e4.z; cn[7] += xv * e4.w;
    }
    #pragma unroll
    for (int off = 16; off > 0; off >>= 1) {
        #pragma unroll
        for (int e = 0; e < E_NUM; e++) {
            cg[e] += __shfl_xor_sync(0xffffffff, cg[e], off);
            cn[e] += __shfl_xor_sync(0xffffffff, cn[e], off);
        }
    }
    if (lane == 0) {
        float noisy[E_NUM];
        #pragma unroll
        for (int e = 0; e < E_NUM; e++) {
            float clean = cg[e] + bg[e];
            float z = cn[e] + bn[e];
            float sp = (z > 0.0f) ? z + log1pf(expf(-z)) : log1pf(expf(z));
            noisy[e] = clean + noise[(size_t)tok * E_NUM + e] * sp;
            out_clean[(size_t)tok * E_NUM + e] = clean;
        }
        int i0 = 0;
        #pragma unroll
        for (int e = 1; e < E_NUM; e++) if (noisy[e] > noisy[i0]) i0 = e;
        int i1 = (i0 == 0) ? 1 : 0;
        #pragma unroll
        for (int e = 0; e < E_NUM; e++)
            if (e != i0 && noisy[e] > noisy[i1]) i1 = e;

        float v0 = noisy[i0], v1 = noisy[i1];
        float e1 = expf(v1 - v0);
        float w0 = 1.0f / (1.0f + e1);
        float w1 = e1 / (1.0f + e1);

        out_idx[(size_t)tok * 2 + 0] = (float)i0;
        out_idx[(size_t)tok * 2 + 1] = (float)i1;

        int p0 = atomicAdd(&g_counts[i0], 1);
        g_tok [i0 * B_MAX + p0] = tok;
        g_gate[i0 * B_MAX + p0] = w0;
        g_pos [tok * 2 + 0] = i0 * B_MAX + p0;
        int p1 = atomicAdd(&g_counts[i1], 1);
        g_tok [i1 * B_MAX + p1] = tok;
        g_gate[i1 * B_MAX + p1] = w1;
        g_pos [tok * 2 + 1] = i1 * B_MAX + p1;
    }
}

// ---------------- prefix scan over 8 experts ----------------
__global__ void scan_kernel() {
    if (threadIdx.x == 0) {
        int s = 0;
        for (int e = 0; e < E_NUM; e++) { g_base[e] = s; s += g_counts[e]; }
        g_base[E_NUM] = s;
    }
}

// =====================================================================
// bf16x3 grouped GEMM: cp.async 2-stage + ldmatrix + mma.sync m16n8k16
// CTA tile 128x128, k-slab 32. 8 warps 2(M)x4(N), warp tile 64x32.
// SMEM: A [m][k] rows padded to 80B; B [k][n] rows padded to 272B.
// =====================================================================
#define OFF_ALO 10240
#define OFF_BHI 20480
#define OFF_BLO 29184
#define STAGE   37888
#define GEMM_DSM (2 * STAGE)

template<int KDIM, int NDIM, bool GATHER, bool SCALE>
__global__ __launch_bounds__(256, 2)
void gemm_bf16_kernel(const __nv_bfloat16* __restrict__ Ahi,
                      const __nv_bfloat16* __restrict__ Alo,
                      const __nv_bfloat16* __restrict__ Whi,
                      const __nv_bfloat16* __restrict__ Wlo,
                      const float* __restrict__ bias,
                      float* __restrict__ Out)
{
    int e   = blockIdx.z;
    int cnt = g_counts[e];
    int m0  = blockIdx.y * 128;
    if (m0 >= cnt) return;
    int n0    = blockIdx.x * 128;
    int gbase = g_base[e];

    extern __shared__ char dsm[];
    uint32_t sb = smem_u32(dsm);
    __shared__ int   s_tok[128];
    __shared__ float s_gate[128];

    int t = threadIdx.x, lane = t & 31, w = t >> 5;
    int wm = (w >> 2) * 64, wn = (w & 3) * 32;
    int g  = lane >> 2,  tt = lane & 3;

    for (int i = t; i < 128; i += 256) {
        int mi = min(m0 + i, cnt - 1);
        if (GATHER) s_tok[i]  = g_tok [e * B_MAX + mi];
        if (SCALE)  s_gate[i] = g_gate[e * B_MAX + mi];
    }
    __syncthreads();

    // --- cp.async source/dst assignments ---
    int R0 = t >> 2, c4 = t & 3;           // A rows R0, R0+64
    size_t rowA0, rowA1;
    if (GATHER) { rowA0 = (size_t)s_tok[R0]; rowA1 = (size_t)s_tok[R0 + 64]; }
    else {
        rowA0 = (size_t)(gbase + min(m0 + R0,      cnt - 1));
        rowA1 = (size_t)(gbase + min(m0 + R0 + 64, cnt - 1));
    }
    const __nv_bfloat16* a0h = Ahi + rowA0 * KDIM + c4 * 8;
    const __nv_bfloat16* a1h = Ahi + rowA1 * KDIM + c4 * 8;
    const __nv_bfloat16* a0l = Alo + rowA0 * KDIM + c4 * 8;
    const __nv_bfloat16* a1l = Alo + rowA1 * KDIM + c4 * 8;
    uint32_t dA0 = R0 * 80 + c4 * 16;
    uint32_t dA1 = (R0 + 64) * 80 + c4 * 16;

    int Rb = t >> 4, c16 = t & 15;         // B rows Rb, Rb+16
    const __nv_bfloat16* b0h = Whi + ((size_t)e * KDIM + Rb)      * NDIM + n0 + c16 * 8;
    const __nv_bfloat16* b1h = Whi + ((size_t)e * KDIM + Rb + 16) * NDIM + n0 + c16 * 8;
    const __nv_bfloat16* b0l = Wlo + ((size_t)e * KDIM + Rb)      * NDIM + n0 + c16 * 8;
    const __nv_bfloat16* b1l = Wlo + ((size_t)e * KDIM + Rb + 16) * NDIM + n0 + c16 * 8;
    uint32_t dB0 = Rb * 272 + c16 * 16;
    uint32_t dB1 = (Rb + 16) * 272 + c16 * 16;

    float acc[4][4][4] = {};
    const int S = KDIM / 32;

#define ISSUE(s_) do { \
        uint32_t base_ = sb + (((s_) & 1) ? STAGE : 0); \
        size_t ka_ = (size_t)(s_) * 32; \
        size_t kb_ = (size_t)(s_) * 32 * NDIM; \
        CP16(base_ + dA0,           a0h + ka_); \
        CP16(base_ + dA1,           a1h + ka_); \
        CP16(base_ + OFF_ALO + dA0, a0l + ka_); \
        CP16(base_ + OFF_ALO + dA1, a1l + ka_); \
        CP16(base_ + OFF_BHI + dB0, b0h + kb_); \
        CP16(base_ + OFF_BHI + dB1, b1h + kb_); \
        CP16(base_ + OFF_BLO + dB0, b0l + kb_); \
        CP16(base_ + OFF_BLO + dB1, b1l + kb_); \
    } while (0)

    ISSUE(0); CPCOMMIT();
    ISSUE(1); CPCOMMIT();

    // ldmatrix per-lane address components
    int Lm = lane & 15, Lh = lane >> 4;
    uint32_t aoff = (uint32_t)(wm + Lm) * 80 + Lh * 16;   // + i*1280 + kh*32
    uint32_t boff = (uint32_t)Lm * 272 + (wn + Lh * 8) * 2; // + kh*4352 + j2*32

    for (int s = 0; s < S; s++) {
        uint32_t base = sb + ((s & 1) ? STAGE : 0);
        CPWAIT1();
        __syncthreads();
        #pragma unroll
        for (int kh = 0; kh < 2; kh++) {
            uint32_t a[4][4], bh[4][2], bl[4][2];
            uint32_t aA = base + aoff + kh * 32;
            #pragma unroll
            for (int i = 0; i < 4; i++) LDSM4(a[i], aA + i * 1280);
            uint32_t bB = base + OFF_BHI + boff + kh * 4352;
            #pragma unroll
            for (int j2 = 0; j2 < 2; j2++) {
                uint32_t r[4]; LDSM4T(r, bB + j2 * 32);
                bh[2*j2][0] = r[0]; bh[2*j2][1] = r[1];
                bh[2*j2+1][0] = r[2]; bh[2*j2+1][1] = r[3];
            }
            uint32_t bL = base + OFF_BLO + boff + kh * 4352;
            #pragma unroll
            for (int j2 = 0; j2 < 2; j2++) {
                uint32_t r[4]; LDSM4T(r, bL + j2 * 32);
                bl[2*j2][0] = r[0]; bl[2*j2][1] = r[1];
                bl[2*j2+1][0] = r[2]; bl[2*j2+1][1] = r[3];
            }
            #pragma unroll
            for (int i = 0; i < 4; i++)
                #pragma unroll
                for (int j = 0; j < 4; j++)
                    mma_bf16(acc[i][j], a[i], bh[j]);
            #pragma unroll
            for (int i = 0; i < 4; i++)
                #pragma unroll
                for (int j = 0; j < 4; j++)
                    mma_bf16(acc[i][j], a[i], bl[j]);
            uint32_t aL = base + OFF_ALO + aoff + kh * 32;
            #pragma unroll
            for (int i = 0; i < 4; i++) LDSM4(a[i], aL + i * 1280);
            #pragma unroll
            for (int i = 0; i < 4; i++)
                #pragma unroll
                for (int j = 0; j < 4; j++)
                    mma_bf16(acc[i][j], a[i], bh[j]);
        }
        __syncthreads();
        if (s + 2 < S) ISSUE(s + 2);
        CPCOMMIT();
    }
#undef ISSUE

    // ---- epilogue ----
    const float* brow = bias + (size_t)e * NDIM + n0;
    #pragma unroll
    for (int i = 0; i < 4; i++) {
        #pragma unroll
        for (int f = 0; f < 2; f++) {
            int rloc = wm + i * 16 + g + f * 8;
            int m = m0 + rloc;
            if (m < cnt) {
                float gw = SCALE ? s_gate[rloc] : 1.0f;
                float* orow = Out + (size_t)(gbase + m) * NDIM + n0;
                #pragma unroll
                for (int j = 0; j < 4; j++) {
                    int col = wn + j * 8 + tt * 2;
                    float2 o;
                    o.x = acc[i][j][f * 2 + 0] + __ldg(brow + col);
                    o.y = acc[i][j][f * 2 + 1] + __ldg(brow + col + 1);
                    if (SCALE) { o.x *= gw; o.y *= gw; }
                    *(float2*)(orow + col) = o;
                }
            }
        }
    }
}

// ---------------- LayerNorm + GELU + bf16 hi/lo split of h ----------------
__global__ void ln_gelu_kernel(const float* __restrict__ ln_g,
                               const float* __restrict__ ln_b)
{
    int r = blockIdx.x;
    int e = 0;
    #pragma unroll
    for (int k = 1; k < E_NUM; k++) if (r >= g_base[k]) e = k;

    float* row = g_hbuf + (size_t)r * H_DIM;
    int t = threadIdx.x;
    float4 v = *(float4*)(row + t * 4);
    float s  = v.x + v.y + v.z + v.w;
    float sq = v.x * v.x + v.y * v.y + v.z * v.z + v.w * v.w;

    __shared__ float ssum[8], ssq[8];
    int lane = t & 31, wid = t >> 5;
    #pragma unroll
    for (int off = 16; off > 0; off >>= 1) {
        s  += __shfl_xor_sync(0xffffffff, s,  off);
        sq += __shfl_xor_sync(0xffffffff, sq, off);
    }
    if (lane == 0) { ssum[wid] = s; ssq[wid] = sq; }
    __syncthreads();
    float S = 0.0f, SQ = 0.0f;
    #pragma unroll
    for (int w = 0; w < 8; w++) { S += ssum[w]; SQ += ssq[w]; }

    float mean = S * (1.0f / H_DIM);
    float var  = SQ * (1.0f / H_DIM) - mean * mean;
    float inv  = 1.0f / sqrtf(var + 1e-5f);

    const float4 g4 = *(const float4*)(ln_g + (size_t)e * H_DIM + t * 4);
    const float4 b4 = *(const float4*)(ln_b + (size_t)e * H_DIM + t * 4);

    float u;
    u = (v.x - mean) * inv * g4.x + b4.x; v.x = 0.5f * u * (1.0f + erff(u * 0.7071067811865475f));
    u = (v.y - mean) * inv * g4.y + b4.y; v.y = 0.5f * u * (1.0f + erff(u * 0.7071067811865475f));
    u = (v.z - mean) * inv * g4.z + b4.z; v.z = 0.5f * u * (1.0f + erff(u * 0.7071067811865475f));
    u = (v.w - mean) * inv * g4.w + b4.w; v.w = 0.5f * u * (1.0f + erff(u * 0.7071067811865475f));

    uint32_t h0 = pack_bf16(v.x, v.y), h1 = pack_bf16(v.z, v.w);
    float2 f0 = unpack_bf16(h0), f1 = unpack_bf16(h1);
    uint32_t l0 = pack_bf16(v.x - f0.x, v.y - f0.y);
    uint32_t l1 = pack_bf16(v.z - f1.x, v.w - f1.y);
    ((uint2*)(g_hs_hi + (size_t)r * H_DIM))[t] = make_uint2(h0, h1);
    ((uint2*)(g_hs_lo + (size_t)r * H_DIM))[t] = make_uint2(l0, l1);
}

// ---------------- combine: out[tok] = obuf[slot0] + obuf[slot1] ----------------
__global__ void combine_kernel(float* __restrict__ out)
{
    int tok = blockIdx.x;
    int enc0 = g_pos[tok * 2], enc1 = g_pos[tok * 2 + 1];
    int s0 = g_base[enc0 >> 13] + (enc0 & (B_MAX - 1));
    int s1 = g_base[enc1 >> 13] + (enc1 & (B_MAX - 1));
    const float4* r0 = (const float4*)(g_obuf + (size_t)s0 * D_DIM);
    const float4* r1 = (const float4*)(g_obuf + (size_t)s1 * D_DIM);
    float4* o = (float4*)(out + (size_t)tok * D_DIM);
    int i = threadIdx.x;                 // 192 threads
    float4 a = r0[i], b = r1[i];
    o[i] = make_float4(a.x + b.x, a.y + b.y, a.z + b.z, a.w + b.w);
}

// ---------------- launch ----------------
extern "C" void kernel_launch(void* const* d_in, const int* in_sizes, int n_in,
                              void* d_out, int out_size)
{
    const float* x     = (const float*)d_in[0];
    const float* noise = (const float*)d_in[1];
    const float* Wg    = (const float*)d_in[2];
    const float* bg    = (const float*)d_in[3];
    const float* Wn    = (const float*)d_in[4];
    const float* bn    = (const float*)d_in[5];
    const float* W1    = (const float*)d_in[6];
    const float* b1    = (const float*)d_in[7];
    const float* lng   = (const float*)d_in[8];
    const float* lnb   = (const float*)d_in[9];
    const float* W2    = (const float*)d_in[10];
    const float* b2    = (const float*)d_in[11];

    float* out = (float*)d_out;
    int B = in_sizes[0] / D_DIM;                      // 8192

    float* out_clean = out + (size_t)B * D_DIM;       // [B, E]
    float* out_idx   = out_clean + (size_t)B * E_NUM; // [B, 2] as float

    __nv_bfloat16 *xs_hi, *xs_lo, *w1_hi, *w1_lo, *w2_hi, *w2_lo, *hs_hi, *hs_lo;
    float *hbuf, *obuf;
    cudaGetSymbolAddress((void**)&xs_hi, g_xs_hi);
    cudaGetSymbolAddress((void**)&xs_lo, g_xs_lo);
    cudaGetSymbolAddress((void**)&w1_hi, g_w1_hi);
    cudaGetSymbolAddress((void**)&w1_lo, g_w1_lo);
    cudaGetSymbolAddress((void**)&w2_hi, g_w2_hi);
    cudaGetSymbolAddress((void**)&w2_lo, g_w2_lo);
    cudaGetSymbolAddress((void**)&hs_hi, g_hs_hi);
    cudaGetSymbolAddress((void**)&hs_lo, g_hs_lo);
    cudaGetSymbolAddress((void**)&hbuf, g_hbuf);
    cudaGetSymbolAddress((void**)&obuf, g_obuf);

    cudaFuncSetAttribute((const void*)gemm_bf16_kernel<D_DIM, H_DIM, true, false>,
                         cudaFuncAttributeMaxDynamicSharedMemorySize, GEMM_DSM);
    cudaFuncSetAttribute((const void*)gemm_bf16_kernel<H_DIM, D_DIM, false, true>,
                         cudaFuncAttributeMaxDynamicSharedMemorySize, GEMM_DSM);

    zero_counters_kernel<<<1, 32>>>();
    gating_kernel<<<(B + 7) / 8, 256>>>(x, noise, Wg, bg, Wn, bn, out_clean, out_idx, B);
    scan_kernel<<<1, 32>>>();

    // one-time operand splits (x, W1, W2) -> bf16 hi/lo
    int nx = B * D_DIM / 4;                 // 1572864
    int nw = E_NUM * D_DIM * H_DIM / 4;     // 1572864
    split_kernel<<<(nx + 255) / 256, 256>>>(x,  xs_hi, xs_lo, nx);
    split_kernel<<<(nw + 255) / 256, 256>>>(W1, w1_hi, w1_lo, nw);
    split_kernel<<<(nw + 255) / 256, 256>>>(W2, w2_hi, w2_lo, nw);

    // gemm1: h = gather(x) @ W1[e] + b1   (N=1024, K=768)
    gemm_bf16_kernel<D_DIM, H_DIM, true, false>
        <<<dim3(H_DIM / 128, B_MAX / 128, E_NUM), 256, GEMM_DSM>>>(
            xs_hi, xs_lo, w1_hi, w1_lo, b1, hbuf);

    ln_gelu_kernel<<<2 * B, 256>>>(lng, lnb);

    // gemm2: obuf = gate * (h @ W2[e] + b2)   (N=768, K=1024)
    gemm_bf16_kernel<H_DIM, D_DIM, false, true>
        <<<dim3(D_DIM / 128, B_MAX / 128, E_NUM), 256, GEMM_DSM>>>(
            hs_hi, hs_lo, w2_hi, w2_lo, b2, obuf);

    combine_kernel<<<B, 192>>>(out);
}